// round 2
// baseline (speedup 1.0000x reference)
#include <cuda_runtime.h>

// Problem constants (match reference)
#define BB   16
#define CC   32
#define HW   384
#define NKK  32
#define HID  128
#define KOUT (NKK * 9)   // 288
#define NSLICE 4

// Scratch (no allocations allowed in kernel_launch)
__device__ float g_part[BB * CC * NSLICE];  // partial sums per plane slice
__device__ float g_kern[BB * NKK * 9];      // [B, NK, 3, 3] generated kernels

// ---------------------------------------------------------------------------
// Kernel 1: partial average pool. grid = (B*C, NSLICE); each block sums its
// quarter of one plane. 2048 blocks -> enough MLP to saturate HBM.
// ---------------------------------------------------------------------------
__global__ void pool_kernel(const float* __restrict__ x) {
    const int bc    = blockIdx.x;
    const int slice = blockIdx.y;
    const int n4    = HW * HW / 4 / NSLICE;           // 9216 float4 per slice
    const float4* p = (const float4*)(x + (size_t)bc * HW * HW) + slice * n4;

    float sum = 0.f;
    #pragma unroll 4
    for (int i = threadIdx.x; i < n4; i += blockDim.x) {
        float4 v = p[i];
        sum += (v.x + v.y) + (v.z + v.w);
    }

    __shared__ float red[8];
    #pragma unroll
    for (int o = 16; o; o >>= 1) sum += __shfl_xor_sync(0xffffffffu, sum, o);
    if ((threadIdx.x & 31) == 0) red[threadIdx.x >> 5] = sum;
    __syncthreads();
    if (threadIdx.x < 32) {
        float s = (threadIdx.x < (blockDim.x >> 5)) ? red[threadIdx.x] : 0.f;
        #pragma unroll
        for (int o = 4; o; o >>= 1) s += __shfl_xor_sync(0xffffffffu, s, o);
        if (threadIdx.x == 0) g_part[bc * NSLICE + slice] = s;
    }
}

// ---------------------------------------------------------------------------
// Kernel 2: reduce partials + tiny MLP -> per-sample depthwise kernels
// One block per batch sample, 288 threads.
// ---------------------------------------------------------------------------
__global__ void mlp_kernel(const float* __restrict__ w1, const float* __restrict__ b1,
                           const float* __restrict__ w2, const float* __restrict__ b2) {
    const int b = blockIdx.x;
    const int t = threadIdx.x;

    __shared__ float pooled_s[CC];
    __shared__ float hdn_s[HID];

    if (t < CC) {
        const float* pp = g_part + (b * CC + t) * NSLICE;
        pooled_s[t] = (pp[0] + pp[1] + pp[2] + pp[3]) * (1.f / (float)(HW * HW));
    }
    __syncthreads();

    if (t < HID) {
        float acc = b1[t];
        #pragma unroll 8
        for (int i = 0; i < CC; i++) acc = fmaf(pooled_s[i], w1[i * HID + t], acc);
        hdn_s[t] = fmaxf(acc, 0.f);
    }
    __syncthreads();

    if (t < KOUT) {
        float acc = b2[t];
        #pragma unroll 8
        for (int i = 0; i < HID; i++) acc = fmaf(hdn_s[i], w2[i * KOUT + t], acc);
        g_kern[b * KOUT + t] = acc;
    }
}

// ---------------------------------------------------------------------------
// Kernel 3: per-sample depthwise 3x3 conv, pad=1.
// Block = (96,4); each thread computes 4 output rows x 4 cols -> block covers
// 16 rows x 384 cols. Halo columns come from warp shuffles (each warp covers
// 128 contiguous columns); only lanes 0 / 31 do a scalar halo load.
// ---------------------------------------------------------------------------
__global__ __launch_bounds__(384)
void conv_kernel(const float* __restrict__ x, float* __restrict__ out) {
    const int plane = blockIdx.y;              // b*NK + nk
    const int b  = plane >> 5;
    const int ch = plane & 31;

    const int tx   = threadIdx.x;              // 0..95 (96 ≡ 0 mod 32, so lane == tx&31)
    const int ty   = threadIdx.y;              // 0..3
    const int lane = tx & 31;
    const int row0 = blockIdx.x * 16 + ty * 4; // first of 4 output rows
    const int col  = tx * 4;

    const float* __restrict__ ip = x   + ((size_t)b * CC + ch) * (size_t)(HW * HW);
    float*       __restrict__ op = out + (size_t)plane * (size_t)(HW * HW);

    float w[9];
    {
        const float* kp = g_kern + plane * 9;
        #pragma unroll
        for (int i = 0; i < 9; i++) w[i] = kp[i];
    }

    // Load 6 input rows: row0-1 .. row0+4. Halo via shuffle.
    float4 c[6];
    float  l[6], r[6];
    #pragma unroll
    for (int i = 0; i < 6; i++) {
        const int y = row0 - 1 + i;
        const bool in = ((unsigned)y < (unsigned)HW);
        float4 v = make_float4(0.f, 0.f, 0.f, 0.f);
        const float* rp = ip + (size_t)y * HW;
        if (in) v = *(const float4*)(rp + col);
        c[i] = v;
        float lv = __shfl_up_sync(0xffffffffu, v.w, 1);
        float rv = __shfl_down_sync(0xffffffffu, v.x, 1);
        if (lane == 0)  lv = (in && col > 0)        ? rp[col - 1] : 0.f;
        if (lane == 31) rv = (in && col + 4 < HW)   ? rp[col + 4] : 0.f;
        l[i] = lv; r[i] = rv;
    }

    #pragma unroll
    for (int orow = 0; orow < 4; orow++) {
        float4 acc = make_float4(0.f, 0.f, 0.f, 0.f);
        #pragma unroll
        for (int dy = 0; dy < 3; dy++) {
            const int i = orow + dy;
            const float w0 = w[dy * 3 + 0];
            const float w1_ = w[dy * 3 + 1];
            const float w2_ = w[dy * 3 + 2];
            const float e0 = l[i];
            const float e1 = c[i].x, e2 = c[i].y, e3 = c[i].z, e4 = c[i].w;
            const float e5 = r[i];
            acc.x = fmaf(w0, e0, fmaf(w1_, e1, fmaf(w2_, e2, acc.x)));
            acc.y = fmaf(w0, e1, fmaf(w1_, e2, fmaf(w2_, e3, acc.y)));
            acc.z = fmaf(w0, e2, fmaf(w1_, e3, fmaf(w2_, e4, acc.z)));
            acc.w = fmaf(w0, e3, fmaf(w1_, e4, fmaf(w2_, e5, acc.w)));
        }
        *(float4*)(op + (size_t)(row0 + orow) * HW + col) = acc;
    }
}

// ---------------------------------------------------------------------------
extern "C" void kernel_launch(void* const* d_in, const int* in_sizes, int n_in,
                              void* d_out, int out_size) {
    const float* x  = (const float*)d_in[0];
    const float* w1 = (const float*)d_in[1];
    const float* b1 = (const float*)d_in[2];
    const float* w2 = (const float*)d_in[3];
    const float* b2 = (const float*)d_in[4];
    float* out = (float*)d_out;

    // 1) pooling partials: 4 blocks per (b,c) plane
    pool_kernel<<<dim3(BB * CC, NSLICE), 256>>>(x);

    // 2) kernel-generator MLP (also reduces partials)
    mlp_kernel<<<BB, KOUT>>>(w1, b1, w2, b2);

    // 3) depthwise dynamic conv: block covers 16 rows x 384 cols of one plane
    dim3 grid(HW / 16, BB * NKK);  // 24 x 512
    dim3 block(96, 4);             // 384 threads
    conv_kernel<<<grid, block>>>(x, out);
}

// round 3
// speedup vs baseline: 1.0522x; 1.0522x over previous
#include <cuda_runtime.h>

// Problem constants (match reference)
#define BB   16
#define CC   32
#define HW   384
#define NKK  32
#define HID  128
#define KOUT (NKK * 9)   // 288
#define NSLICE 4

// Conv tile geometry
#define TR   16                 // output rows per block
#define SW   392                // smem row stride in floats (image col c -> index c+4)
#define SOFF 4                  // left pad (keeps float4 STS aligned, holds zero halo)

// Scratch (no allocations allowed in kernel_launch)
__device__ float g_part[BB * CC * NSLICE];  // partial sums per plane slice
__device__ float g_kern[BB * NKK * 9];      // [B, NK, 3, 3] generated kernels

// ---------------------------------------------------------------------------
// Kernel 1: partial average pool. grid = (B*C, NSLICE). At DRAM cap already.
// ---------------------------------------------------------------------------
__global__ void pool_kernel(const float* __restrict__ x) {
    const int bc    = blockIdx.x;
    const int slice = blockIdx.y;
    const int n4    = HW * HW / 4 / NSLICE;           // 9216 float4 per slice
    const float4* p = (const float4*)(x + (size_t)bc * HW * HW) + slice * n4;

    float sum = 0.f;
    #pragma unroll 4
    for (int i = threadIdx.x; i < n4; i += blockDim.x) {
        float4 v = p[i];
        sum += (v.x + v.y) + (v.z + v.w);
    }

    __shared__ float red[8];
    #pragma unroll
    for (int o = 16; o; o >>= 1) sum += __shfl_xor_sync(0xffffffffu, sum, o);
    if ((threadIdx.x & 31) == 0) red[threadIdx.x >> 5] = sum;
    __syncthreads();
    if (threadIdx.x < 32) {
        float s = (threadIdx.x < (blockDim.x >> 5)) ? red[threadIdx.x] : 0.f;
        #pragma unroll
        for (int o = 4; o; o >>= 1) s += __shfl_xor_sync(0xffffffffu, s, o);
        if (threadIdx.x == 0) g_part[bc * NSLICE + slice] = s;
    }
}

// ---------------------------------------------------------------------------
// Kernel 2: reduce partials + tiny MLP -> per-sample depthwise kernels
// ---------------------------------------------------------------------------
__global__ void mlp_kernel(const float* __restrict__ w1, const float* __restrict__ b1,
                           const float* __restrict__ w2, const float* __restrict__ b2) {
    const int b = blockIdx.x;
    const int t = threadIdx.x;

    __shared__ float pooled_s[CC];
    __shared__ float hdn_s[HID];

    if (t < CC) {
        const float* pp = g_part + (b * CC + t) * NSLICE;
        pooled_s[t] = (pp[0] + pp[1] + pp[2] + pp[3]) * (1.f / (float)(HW * HW));
    }
    __syncthreads();

    if (t < HID) {
        float acc = b1[t];
        #pragma unroll 8
        for (int i = 0; i < CC; i++) acc = fmaf(pooled_s[i], w1[i * HID + t], acc);
        hdn_s[t] = fmaxf(acc, 0.f);
    }
    __syncthreads();

    if (t < KOUT) {
        float acc = b2[t];
        #pragma unroll 8
        for (int i = 0; i < HID; i++) acc = fmaf(hdn_s[i], w2[i * KOUT + t], acc);
        g_kern[b * KOUT + t] = acc;
    }
}

// ---------------------------------------------------------------------------
// Kernel 3: per-sample depthwise 3x3 conv, pad=1, smem-tiled.
// Block (96,4) = 384 thr covers TR=16 output rows x 384 cols of one plane.
// Stage 1: coalesced float4 loads of the 18-row halo tile into smem.
// Stage 2: each thread computes 4 rows x 4 cols from smem (rolling 3-row
//          register window; 1 aligned LDS.128 + 2 scalar LDS per row).
// ---------------------------------------------------------------------------
__global__ __launch_bounds__(384, 4)
void conv_kernel(const float* __restrict__ x, float* __restrict__ out) {
    __shared__ float s[(TR + 2) * SW];

    const int plane = blockIdx.y;              // b*NK + nk
    const int b  = plane >> 5;
    const int ch = plane & 31;

    const int tx   = threadIdx.x;              // 0..95
    const int ty   = threadIdx.y;              // 0..3
    const int tid  = tx + 96 * ty;             // 0..383
    const int rb   = blockIdx.x * TR;          // first output row of block

    const float* __restrict__ ip = x   + ((size_t)b * CC + ch) * (size_t)(HW * HW);
    float*       __restrict__ op = out + (size_t)plane * (size_t)(HW * HW);

    // Zero the 4-float halo columns on both sides of each of the 18 rows.
    if (tid < (TR + 2) * 2) {
        const int lr   = tid >> 1;
        const int side = tid & 1;
        *(float4*)&s[lr * SW + (side ? (SOFF + HW) : 0)] = make_float4(0.f, 0.f, 0.f, 0.f);
    }

    // Coalesced tile load: 18 rows x 96 float4 = 1728 float4, 384 threads.
    #pragma unroll
    for (int k = 0; k < 5; k++) {              // ceil(1728/384) = 5 iters (last partial)
        const int idx = tid + k * 384;
        if (idx < (TR + 2) * 96) {
            const int lr = idx / 96;           // local row 0..17
            const int c4 = idx % 96;           // float4 column
            const int y  = rb - 1 + lr;
            float4 v = make_float4(0.f, 0.f, 0.f, 0.f);
            if ((unsigned)y < (unsigned)HW)
                v = *(const float4*)(ip + (size_t)y * HW + c4 * 4);
            *(float4*)&s[lr * SW + SOFF + c4 * 4] = v;
        }
    }

    float w[9];
    {
        const float* kp = g_kern + plane * 9;
        #pragma unroll
        for (int i = 0; i < 9; i++) w[i] = kp[i];
    }
    __syncthreads();

    const int col  = tx * 4;                   // output columns col..col+3
    const int lr0  = ty * 4;                   // first smem row needed (= row0-1 local)
    const float* sp = s + lr0 * SW + SOFF + col;

    // Rolling 3-row window: e[i] = {left, x0, x1, x2, x3, right}
    float e[3][6];
    #pragma unroll
    for (int i = 0; i < 2; i++) {
        const float* rp = sp + i * SW;
        float4 v = *(const float4*)rp;
        e[i][0] = rp[-1]; e[i][1] = v.x; e[i][2] = v.y; e[i][3] = v.z; e[i][4] = v.w; e[i][5] = rp[4];
    }

    #pragma unroll
    for (int orow = 0; orow < 4; orow++) {
        {   // load bottom row of the window
            const int i = (orow + 2) % 3;
            const float* rp = sp + (orow + 2) * SW;
            float4 v = *(const float4*)rp;
            e[i][0] = rp[-1]; e[i][1] = v.x; e[i][2] = v.y; e[i][3] = v.z; e[i][4] = v.w; e[i][5] = rp[4];
        }
        float4 acc = make_float4(0.f, 0.f, 0.f, 0.f);
        #pragma unroll
        for (int dy = 0; dy < 3; dy++) {
            const float* ee = e[(orow + dy) % 3];
            const float w0 = w[dy * 3 + 0];
            const float w1_ = w[dy * 3 + 1];
            const float w2_ = w[dy * 3 + 2];
            acc.x = fmaf(w0, ee[0], fmaf(w1_, ee[1], fmaf(w2_, ee[2], acc.x)));
            acc.y = fmaf(w0, ee[1], fmaf(w1_, ee[2], fmaf(w2_, ee[3], acc.y)));
            acc.z = fmaf(w0, ee[2], fmaf(w1_, ee[3], fmaf(w2_, ee[4], acc.z)));
            acc.w = fmaf(w0, ee[3], fmaf(w1_, ee[4], fmaf(w2_, ee[5], acc.w)));
        }
        *(float4*)(op + (size_t)(rb + ty * 4 + orow) * HW + col) = acc;
    }
}

// ---------------------------------------------------------------------------
extern "C" void kernel_launch(void* const* d_in, const int* in_sizes, int n_in,
                              void* d_out, int out_size) {
    const float* x  = (const float*)d_in[0];
    const float* w1 = (const float*)d_in[1];
    const float* b1 = (const float*)d_in[2];
    const float* w2 = (const float*)d_in[3];
    const float* b2 = (const float*)d_in[4];
    float* out = (float*)d_out;

    pool_kernel<<<dim3(BB * CC, NSLICE), 256>>>(x);
    mlp_kernel<<<BB, KOUT>>>(w1, b1, w2, b2);

    dim3 grid(HW / TR, BB * NKK);  // 24 x 512
    dim3 block(96, 4);             // 384 threads
    conv_kernel<<<grid, block>>>(x, out);
}

// round 4
// speedup vs baseline: 1.1687x; 1.1107x over previous
#include <cuda_runtime.h>

// Problem constants (match reference)
#define BB   16
#define CC   32
#define HW   384
#define NKK  32
#define HID  128
#define KOUT (NKK * 9)   // 288
#define NSLICE 4

// Conv strip geometry: each warp covers 128 cols x SR rows of one plane.
#define SR   32
#define STRIPS_PER_PLANE (3 * (HW / SR))   // 3 col-strips x 12 row-strips = 36

// Scratch (no allocations allowed in kernel_launch)
__device__ float g_part[BB * CC * NSLICE];  // partial sums per plane slice
__device__ float g_kern[BB * NKK * 9];      // [B, NK, 3, 3] generated kernels

// ---------------------------------------------------------------------------
// Kernel 1: partial average pool. grid = (B*C, NSLICE). At DRAM read cap.
// ---------------------------------------------------------------------------
__global__ void pool_kernel(const float* __restrict__ x) {
    const int bc    = blockIdx.x;
    const int slice = blockIdx.y;
    const int n4    = HW * HW / 4 / NSLICE;           // 9216 float4 per slice
    const float4* p = (const float4*)(x + (size_t)bc * HW * HW) + slice * n4;

    float sum = 0.f;
    #pragma unroll 4
    for (int i = threadIdx.x; i < n4; i += blockDim.x) {
        float4 v = p[i];
        sum += (v.x + v.y) + (v.z + v.w);
    }

    __shared__ float red[8];
    #pragma unroll
    for (int o = 16; o; o >>= 1) sum += __shfl_xor_sync(0xffffffffu, sum, o);
    if ((threadIdx.x & 31) == 0) red[threadIdx.x >> 5] = sum;
    __syncthreads();
    if (threadIdx.x < 32) {
        float s = (threadIdx.x < (blockDim.x >> 5)) ? red[threadIdx.x] : 0.f;
        #pragma unroll
        for (int o = 4; o; o >>= 1) s += __shfl_xor_sync(0xffffffffu, s, o);
        if (threadIdx.x == 0) g_part[bc * NSLICE + slice] = s;
    }
}

// ---------------------------------------------------------------------------
// Kernel 2: reduce partials + tiny MLP -> per-sample depthwise kernels
// ---------------------------------------------------------------------------
__global__ void mlp_kernel(const float* __restrict__ w1, const float* __restrict__ b1,
                           const float* __restrict__ w2, const float* __restrict__ b2) {
    const int b = blockIdx.x;
    const int t = threadIdx.x;

    __shared__ float pooled_s[CC];
    __shared__ float hdn_s[HID];

    if (t < CC) {
        const float* pp = g_part + (b * CC + t) * NSLICE;
        pooled_s[t] = (pp[0] + pp[1] + pp[2] + pp[3]) * (1.f / (float)(HW * HW));
    }
    __syncthreads();

    if (t < HID) {
        float acc = b1[t];
        #pragma unroll 8
        for (int i = 0; i < CC; i++) acc = fmaf(pooled_s[i], w1[i * HID + t], acc);
        hdn_s[t] = fmaxf(acc, 0.f);
    }
    __syncthreads();

    if (t < KOUT) {
        float acc = b2[t];
        #pragma unroll 8
        for (int i = 0; i < HID; i++) acc = fmaf(hdn_s[i], w2[i * KOUT + t], acc);
        g_kern[b * KOUT + t] = acc;
    }
}

// ---------------------------------------------------------------------------
// Kernel 3: per-sample depthwise 3x3 conv, pad=1.
// Direct-gmem rolling-register design: each warp owns a 128-col x SR-row
// strip, marching down rows with a 3-row register window and 1-row prefetch.
// No smem, no shuffles. Per thread per row: 1 float4 + 2 scalar LDG,
// 1 float4 streaming STG.
// ---------------------------------------------------------------------------
struct RowV { float l; float4 c; float r; };

__device__ __forceinline__ RowV load_row(const float* __restrict__ ip,
                                         int y, int gcol) {
    RowV v;
    if ((unsigned)y < (unsigned)HW) {
        const float* rp = ip + (size_t)y * HW + gcol;
        v.c = *(const float4*)rp;
        v.l = (gcol > 0)        ? rp[-1] : 0.f;
        v.r = (gcol + 4 < HW)   ? rp[4]  : 0.f;
    } else {
        v.c = make_float4(0.f, 0.f, 0.f, 0.f);
        v.l = 0.f; v.r = 0.f;
    }
    return v;
}

__device__ __forceinline__ void accum_row(float4& acc, const RowV& v,
                                          float w0, float w1, float w2) {
    acc.x = fmaf(w0, v.l,   fmaf(w1, v.c.x, fmaf(w2, v.c.y, acc.x)));
    acc.y = fmaf(w0, v.c.x, fmaf(w1, v.c.y, fmaf(w2, v.c.z, acc.y)));
    acc.z = fmaf(w0, v.c.y, fmaf(w1, v.c.z, fmaf(w2, v.c.w, acc.z)));
    acc.w = fmaf(w0, v.c.z, fmaf(w1, v.c.w, fmaf(w2, v.r,   acc.w)));
}

__global__ __launch_bounds__(256)
void conv_kernel(const float* __restrict__ x, float* __restrict__ out) {
    const int wid  = (blockIdx.x << 3) + (threadIdx.x >> 5);  // global warp id
    const int lane = threadIdx.x & 31;

    const int plane = wid / STRIPS_PER_PLANE;          // 0..511
    const int rem   = wid % STRIPS_PER_PLANE;          // 0..35
    const int cstrip = rem % 3;                        // col strip (128 cols)
    const int rstrip = rem / 3;                        // row strip (SR rows)

    const int b  = plane >> 5;
    const int ch = plane & 31;
    const int gcol = cstrip * 128 + lane * 4;
    const int r0   = rstrip * SR;

    const float* __restrict__ ip = x   + ((size_t)b * CC + ch) * (size_t)(HW * HW);
    float*       __restrict__ op = out + (size_t)plane * (size_t)(HW * HW) + gcol;

    float w[9];
    {
        const float* kp = g_kern + plane * 9;
        #pragma unroll
        for (int i = 0; i < 9; i++) w[i] = kp[i];
    }

    RowV a = load_row(ip, r0 - 1, gcol);
    RowV bb = load_row(ip, r0,     gcol);
    RowV c = load_row(ip, r0 + 1, gcol);

    #pragma unroll 4
    for (int i = 0; i < SR; i++) {
        RowV d = load_row(ip, r0 + 2 + i, gcol);   // prefetch next (guarded OOB)
        float4 acc = make_float4(0.f, 0.f, 0.f, 0.f);
        accum_row(acc, a,  w[0], w[1], w[2]);
        accum_row(acc, bb, w[3], w[4], w[5]);
        accum_row(acc, c,  w[6], w[7], w[8]);
        __stcs((float4*)(op + (size_t)(r0 + i) * HW), acc);
        a = bb; bb = c; c = d;
    }
}

// ---------------------------------------------------------------------------
extern "C" void kernel_launch(void* const* d_in, const int* in_sizes, int n_in,
                              void* d_out, int out_size) {
    const float* x  = (const float*)d_in[0];
    const float* w1 = (const float*)d_in[1];
    const float* b1 = (const float*)d_in[2];
    const float* w2 = (const float*)d_in[3];
    const float* b2 = (const float*)d_in[4];
    float* out = (float*)d_out;

    pool_kernel<<<dim3(BB * CC, NSLICE), 256>>>(x);
    mlp_kernel<<<BB, KOUT>>>(w1, b1, w2, b2);

    // 512 planes * 36 strips = 18432 warps = 2304 blocks of 8 warps
    const int total_warps = BB * NKK * STRIPS_PER_PLANE;
    conv_kernel<<<total_warps / 8, 256>>>(x, out);
}